// round 1
// baseline (speedup 1.0000x reference)
#include <cuda_runtime.h>
#include <math.h>

#define NTOK  1024
#define CDIM  384
#define DPAIR 128
#define HEADS 12
#define CH    32
#define PROJW 1472   // 384*3 + 144*2 = 1440, padded to 23*64
#define LEPS  1e-5f

// ---------------- scratch (device globals; no allocations allowed) ----------------
__device__ __align__(16) float g_wcat[CDIM * PROJW];
__device__ __align__(16) float g_bcat[PROJW];
__device__ __align__(16) float g_wpT[HEADS * DPAIR];           // Wp transposed [h][d]
__device__ __align__(16) float g_proj[NTOK * PROJW];           // q|k|v|qpts|kpts
__device__ __align__(16) float g_qg[NTOK * HEADS * 12];        // [n][h][y*4+p]
__device__ __align__(16) float g_sq[NTOK * HEADS];             // [n][h]
__device__ __align__(16) float g_kgT[HEADS * NTOK * 12];       // [h][m][12]
__device__ __align__(16) float g_skT[HEADS * NTOK];            // [h][m]
__device__ __align__(16) float g_bias[(size_t)HEADS * NTOK * NTOK]; // [h][n][m] (50MB)
__device__ __align__(16) float g_wt[NTOK * CDIM];              // attention output
__device__ __align__(16) float g_o[NTOK * CDIM];               // after Wo

// ---------------- prep: concat weights, transpose Wp ----------------
__global__ void prep_kernel(const float* __restrict__ Wq, const float* __restrict__ Wk,
                            const float* __restrict__ Wv, const float* __restrict__ Wpq,
                            const float* __restrict__ Wpk,
                            const float* __restrict__ bq, const float* __restrict__ bk,
                            const float* __restrict__ bv, const float* __restrict__ bpq,
                            const float* __restrict__ bpk, const float* __restrict__ Wp) {
    int i = blockIdx.x * blockDim.x + threadIdx.x;
    int stride = gridDim.x * blockDim.x;
    for (int e = i; e < CDIM * PROJW; e += stride) {
        int kk = e / PROJW, j = e % PROJW;
        float v = 0.f;
        if (j < 384)       v = Wq[kk * 384 + j];
        else if (j < 768)  v = Wk[kk * 384 + j - 384];
        else if (j < 1152) v = Wv[kk * 384 + j - 768];
        else if (j < 1296) v = Wpq[kk * 144 + j - 1152];
        else if (j < 1440) v = Wpk[kk * 144 + j - 1296];
        g_wcat[e] = v;
    }
    if (i < PROJW) {
        int j = i; float v = 0.f;
        if (j < 384)       v = bq[j];
        else if (j < 768)  v = bk[j - 384];
        else if (j < 1152) v = bv[j - 768];
        else if (j < 1296) v = bpq[j - 1152];
        else if (j < 1440) v = bpk[j - 1296];
        g_bcat[j] = v;
    }
    if (i < DPAIR * HEADS) {             // Wp [d][h] -> g_wpT [h][d]
        g_wpT[(i % HEADS) * DPAIR + (i / HEADS)] = Wp[i];
    }
}

// ---------------- generic fp32 GEMM: C[M,N] = A[M,K]@B[K,N] + bias ----------------
// BM=BN=64, BK=16, 256 threads, 4x4 micro-tile. M,N multiples of 64; K multiple of 16.
__global__ __launch_bounds__(256) void gemm_kernel(
    const float* __restrict__ A, int lda,
    const float* __restrict__ B, int ldb,
    const float* __restrict__ bias,
    float* __restrict__ C, int ldc, int K) {
    __shared__ __align__(16) float As[16 * 64];
    __shared__ __align__(16) float Bs[16 * 64];
    int t = threadIdx.x;
    int tx = t & 15, ty = t >> 4;
    int row0 = blockIdx.y * 64, col0 = blockIdx.x * 64;
    int arow = t >> 2, ak4 = t & 3;
    int bk = t >> 4, bc4 = t & 15;
    float acc[4][4];
#pragma unroll
    for (int i = 0; i < 4; i++)
#pragma unroll
        for (int j = 0; j < 4; j++) acc[i][j] = 0.f;

    for (int k0 = 0; k0 < K; k0 += 16) {
        float4 av = *reinterpret_cast<const float4*>(A + (row0 + arow) * lda + k0 + ak4 * 4);
        float4 bv = *reinterpret_cast<const float4*>(B + (k0 + bk) * ldb + col0 + bc4 * 4);
        __syncthreads();
        As[(ak4 * 4 + 0) * 64 + arow] = av.x;
        As[(ak4 * 4 + 1) * 64 + arow] = av.y;
        As[(ak4 * 4 + 2) * 64 + arow] = av.z;
        As[(ak4 * 4 + 3) * 64 + arow] = av.w;
        *reinterpret_cast<float4*>(&Bs[bk * 64 + bc4 * 4]) = bv;
        __syncthreads();
#pragma unroll
        for (int kk = 0; kk < 16; kk++) {
            float4 a = *reinterpret_cast<const float4*>(&As[kk * 64 + ty * 4]);
            float4 b = *reinterpret_cast<const float4*>(&Bs[kk * 64 + tx * 4]);
            acc[0][0] += a.x * b.x; acc[0][1] += a.x * b.y; acc[0][2] += a.x * b.z; acc[0][3] += a.x * b.w;
            acc[1][0] += a.y * b.x; acc[1][1] += a.y * b.y; acc[1][2] += a.y * b.z; acc[1][3] += a.y * b.w;
            acc[2][0] += a.z * b.x; acc[2][1] += a.z * b.y; acc[2][2] += a.z * b.z; acc[2][3] += a.z * b.w;
            acc[3][0] += a.w * b.x; acc[3][1] += a.w * b.y; acc[3][2] += a.w * b.z; acc[3][3] += a.w * b.w;
        }
    }
    float4 bb = *reinterpret_cast<const float4*>(bias + col0 + tx * 4);
#pragma unroll
    for (int i = 0; i < 4; i++) {
        float4 cv = make_float4(acc[i][0] + bb.x, acc[i][1] + bb.y,
                                acc[i][2] + bb.z, acc[i][3] + bb.w);
        *reinterpret_cast<float4*>(C + (row0 + ty * 4 + i) * ldc + col0 + tx * 4) = cv;
    }
}

// ---------------- rotate points, compute sq/sk ----------------
__global__ void rotate_kernel(const float* __restrict__ rot) {
    int idx = blockIdx.x * blockDim.x + threadIdx.x;
    if (idx >= NTOK * HEADS) return;
    int n = idx / HEADS, h = idx % HEADS;
    const float* R  = rot + n * 9;
    const float* qp = g_proj + n * PROJW + 1152 + h * 12;
    const float* kp = g_proj + n * PROJW + 1296 + h * 12;
    float* qg = g_qg + idx * 12;
    float* kg = g_kgT + (h * NTOK + n) * 12;
    float sq = 0.f, sk = 0.f;
#pragma unroll
    for (int y = 0; y < 3; y++) {
        float r0 = R[y * 3 + 0], r1 = R[y * 3 + 1], r2 = R[y * 3 + 2];
#pragma unroll
        for (int p = 0; p < 4; p++) {
            float a = r0 * qp[p] + r1 * qp[4 + p] + r2 * qp[8 + p];
            qg[y * 4 + p] = a; sq += a * a;
            float b = r0 * kp[p] + r1 * kp[4 + p] + r2 * kp[8 + p];
            kg[y * 4 + p] = b; sk += b * b;
        }
    }
    g_sq[idx] = sq;
    g_skT[h * NTOK + n] = sk;
}

// ---------------- pair bias: bias[h][n][m] = pair[n][m][:]@Wp[:,h] + bp[h] ----------------
// block: 128 threads, one n, 64 m's. smem-staged, conflict-free (row stride 33 float4).
__global__ __launch_bounds__(128) void pair_bias_kernel(const float* __restrict__ pair,
                                                        const float* __restrict__ bp) {
    __shared__ __align__(16) float sp[64 * 132];      // 64 m x 128 d, padded
    __shared__ __align__(16) float swpT[HEADS * DPAIR];
    int t = threadIdx.x;
    int n = blockIdx.y;
    int m0 = blockIdx.x * 64;

    for (int i = t; i < HEADS * DPAIR; i += 128) swpT[i] = g_wpT[i];

    const float4* src = reinterpret_cast<const float4*>(pair + ((size_t)n * NTOK + m0) * DPAIR);
    float4* sp4 = reinterpret_cast<float4*>(sp);
#pragma unroll
    for (int i = 0; i < 16; i++) {
        int idx = t + i * 128;
        int ml = idx >> 5, d4 = idx & 31;
        sp4[ml * 33 + d4] = src[idx];
    }
    __syncthreads();

    int m = t & 63, h0 = (t >> 6) * 6;
    float acc[6] = {0.f, 0.f, 0.f, 0.f, 0.f, 0.f};
    const float4* wp4 = reinterpret_cast<const float4*>(swpT);
#pragma unroll 4
    for (int d4 = 0; d4 < 32; d4++) {
        float4 pv = sp4[m * 33 + d4];
#pragma unroll
        for (int j = 0; j < 6; j++) {
            float4 w = wp4[(h0 + j) * 32 + d4];
            acc[j] += pv.x * w.x; acc[j] += pv.y * w.y;
            acc[j] += pv.z * w.z; acc[j] += pv.w * w.w;
        }
    }
#pragma unroll
    for (int j = 0; j < 6; j++)
        g_bias[((size_t)(h0 + j) * NTOK + n) * NTOK + m0 + m] = acc[j] + bp[h0 + j];
}

// ---------------- fused attention (flash-style, thread-per-row) ----------------
// grid (16 nblocks, 12 heads), 64 threads. 32-wide m tiles through smem.
__global__ __launch_bounds__(64) void attn_kernel() {
    __shared__ __align__(16) float ks[32 * 32];
    __shared__ __align__(16) float vs[32 * 32];
    __shared__ __align__(16) float kgs[32 * 12];
    __shared__ __align__(16) float sks[32];
    __shared__ __align__(16) float bt[64 * 33];
    int t = threadIdx.x;
    int h = blockIdx.y;
    int n = blockIdx.x * 64 + t;

    const float SC  = 0.17677669529663687f;   // 32^-0.5
    const float L2E = 1.4426950408889634f;
    const float SCL = SC * L2E;

    float4 q4[8];
    const float4* qp4 = reinterpret_cast<const float4*>(g_proj + n * PROJW + h * CH);
#pragma unroll
    for (int c4 = 0; c4 < 8; c4++) q4[c4] = qp4[c4];
    float4 qg4[3];
    const float4* qgp = reinterpret_cast<const float4*>(g_qg + (n * HEADS + h) * 12);
#pragma unroll
    for (int i = 0; i < 3; i++) qg4[i] = qgp[i];
    float sqv = g_sq[n * HEADS + h];
    float base = -0.5f * SCL * sqv;

    float mmax = -1e30f, lsum = 0.f;
    float acc[32];
#pragma unroll
    for (int c = 0; c < 32; c++) acc[c] = 0.f;

    const float4* gp4 = reinterpret_cast<const float4*>(g_proj);

    for (int mt = 0; mt < NTOK / 32; mt++) {
        int m0 = mt * 32;
        __syncthreads();
        // stage k, v tiles
#pragma unroll
        for (int i = 0; i < 4; i++) {
            int idx = t + i * 64;
            int ml = idx >> 3, c4 = idx & 7;
            ((float4*)ks)[ml * 8 + c4] = gp4[((m0 + ml) * PROJW + 384 + h * CH) / 4 + c4];
            ((float4*)vs)[ml * 8 + c4] = gp4[((m0 + ml) * PROJW + 768 + h * CH) / 4 + c4];
        }
        {   // kg tile: 96 float4
            const float4* kgp = reinterpret_cast<const float4*>(g_kgT + (h * NTOK + m0) * 12);
            for (int i = t; i < 96; i += 64) ((float4*)kgs)[i] = kgp[i];
        }
        if (t < 32) sks[t] = g_skT[h * NTOK + m0 + t];
        {   // bias tile [64 rows][32 m], coalesced
            const float* bsrc = g_bias + ((size_t)h * NTOK + blockIdx.x * 64) * NTOK + m0;
#pragma unroll
            for (int i = 0; i < 8; i++) {
                int idx = t + i * 64;
                int row = idx >> 3, c4 = idx & 7;
                float4 bv = *reinterpret_cast<const float4*>(bsrc + (size_t)row * NTOK + c4 * 4);
                bt[row * 33 + c4 * 4 + 0] = bv.x;
                bt[row * 33 + c4 * 4 + 1] = bv.y;
                bt[row * 33 + c4 * 4 + 2] = bv.z;
                bt[row * 33 + c4 * 4 + 3] = bv.w;
            }
        }
        __syncthreads();

        float sreg[32];
        float tmax = -1e30f;
#pragma unroll
        for (int j = 0; j < 32; j++) {
            float d = 0.f;
#pragma unroll
            for (int c4 = 0; c4 < 8; c4++) {
                float4 kv = ((const float4*)ks)[j * 8 + c4];
                d += q4[c4].x * kv.x; d += q4[c4].y * kv.y;
                d += q4[c4].z * kv.z; d += q4[c4].w * kv.w;
            }
#pragma unroll
            for (int i = 0; i < 3; i++) {
                float4 kg = ((const float4*)kgs)[j * 3 + i];
                d += qg4[i].x * kg.x; d += qg4[i].y * kg.y;
                d += qg4[i].z * kg.z; d += qg4[i].w * kg.w;
            }
            float s = SCL * d + base - 0.5f * SCL * sks[j] + L2E * bt[t * 33 + j];
            sreg[j] = s;
            tmax = fmaxf(tmax, s);
        }
        float newmax = fmaxf(mmax, tmax);
        float corr = exp2f(mmax - newmax);
        lsum *= corr;
#pragma unroll
        for (int c = 0; c < 32; c++) acc[c] *= corr;
        mmax = newmax;
#pragma unroll
        for (int j = 0; j < 32; j++) {
            float p = exp2f(sreg[j] - mmax);
            lsum += p;
#pragma unroll
            for (int c4 = 0; c4 < 8; c4++) {
                float4 vv = ((const float4*)vs)[j * 8 + c4];
                acc[c4 * 4 + 0] += p * vv.x; acc[c4 * 4 + 1] += p * vv.y;
                acc[c4 * 4 + 2] += p * vv.z; acc[c4 * 4 + 3] += p * vv.w;
            }
        }
    }
    float inv = 1.f / lsum;
    float4* o4 = reinterpret_cast<float4*>(g_wt + n * CDIM + h * CH);
#pragma unroll
    for (int c4 = 0; c4 < 8; c4++)
        o4[c4] = make_float4(acc[c4 * 4 + 0] * inv, acc[c4 * 4 + 1] * inv,
                             acc[c4 * 4 + 2] * inv, acc[c4 * 4 + 3] * inv);
}

// ---------------- residual + LayerNorm ----------------
__global__ __launch_bounds__(128) void ln_kernel(const float* __restrict__ single,
                                                 const float* __restrict__ gamma,
                                                 const float* __restrict__ beta,
                                                 float* __restrict__ out) {
    __shared__ float xr[CDIM];
    __shared__ float red[4];
    int n = blockIdx.x, t = threadIdx.x;
    float s = 0.f;
    for (int c = t; c < CDIM; c += 128) {
        float x = single[n * CDIM + c] + g_o[n * CDIM + c];
        xr[c] = x; s += x;
    }
#pragma unroll
    for (int o = 16; o > 0; o >>= 1) s += __shfl_xor_sync(0xffffffffu, s, o);
    if ((t & 31) == 0) red[t >> 5] = s;
    __syncthreads();
    float mu = (red[0] + red[1] + red[2] + red[3]) * (1.f / CDIM);
    float v = 0.f;
    for (int c = t; c < CDIM; c += 128) { float d = xr[c] - mu; v += d * d; }
#pragma unroll
    for (int o = 16; o > 0; o >>= 1) v += __shfl_xor_sync(0xffffffffu, v, o);
    __syncthreads();
    if ((t & 31) == 0) red[t >> 5] = v;
    __syncthreads();
    float var = (red[0] + red[1] + red[2] + red[3]) * (1.f / CDIM);
    float inv = rsqrtf(var + LEPS);
    for (int c = t; c < CDIM; c += 128)
        out[n * CDIM + c] = (xr[c] - mu) * inv * gamma[c] + beta[c];
}

// ---------------- launch ----------------
extern "C" void kernel_launch(void* const* d_in, const int* in_sizes, int n_in,
                              void* d_out, int out_size) {
    (void)in_sizes; (void)n_in; (void)out_size;
    const float* single = (const float*)d_in[0];
    const float* pair   = (const float*)d_in[1];
    const float* rot    = (const float*)d_in[2];
    // d_in[3] translations: unused by the reference
    const float* Wq  = (const float*)d_in[4];  const float* bq  = (const float*)d_in[5];
    const float* Wk  = (const float*)d_in[6];  const float* bk  = (const float*)d_in[7];
    const float* Wv  = (const float*)d_in[8];  const float* bv  = (const float*)d_in[9];
    const float* Wp  = (const float*)d_in[10]; const float* bp  = (const float*)d_in[11];
    const float* Wpq = (const float*)d_in[12]; const float* bpq = (const float*)d_in[13];
    const float* Wpk = (const float*)d_in[14]; const float* bpk = (const float*)d_in[15];
    const float* Wo  = (const float*)d_in[16]; const float* bo  = (const float*)d_in[17];
    const float* gamma = (const float*)d_in[18];
    const float* beta  = (const float*)d_in[19];
    float* out = (float*)d_out;

    float *p_wcat, *p_bcat, *p_proj, *p_wt, *p_o;
    cudaGetSymbolAddress((void**)&p_wcat, g_wcat);
    cudaGetSymbolAddress((void**)&p_bcat, g_bcat);
    cudaGetSymbolAddress((void**)&p_proj, g_proj);
    cudaGetSymbolAddress((void**)&p_wt, g_wt);
    cudaGetSymbolAddress((void**)&p_o, g_o);

    prep_kernel<<<64, 256>>>(Wq, Wk, Wv, Wpq, Wpk, bq, bk, bv, bpq, bpk, Wp);
    gemm_kernel<<<dim3(PROJW / 64, NTOK / 64), 256>>>(single, CDIM, p_wcat, PROJW,
                                                      p_bcat, p_proj, PROJW, CDIM);
    rotate_kernel<<<48, 256>>>(rot);
    pair_bias_kernel<<<dim3(16, NTOK), 128>>>(pair, bp);
    attn_kernel<<<dim3(16, HEADS), 64>>>();
    gemm_kernel<<<dim3(CDIM / 64, NTOK / 64), 256>>>(p_wt, CDIM, Wo, CDIM,
                                                     bo, p_o, CDIM, CDIM);
    ln_kernel<<<NTOK, 128>>>(single, gamma, beta, out);
}

// round 17
// speedup vs baseline: 1.3247x; 1.3247x over previous
#include <cuda_runtime.h>
#include <math.h>

#define NTOK  1024
#define CDIM  384
#define DPAIR 128
#define HEADS 12
#define CH    32
#define PROJW 1472   // 384*3 + 144*2 = 1440, padded to 23*64
#define LEPS  1e-5f

// ---------------- scratch (device globals; no allocations allowed) ----------------
__device__ __align__(16) float g_wcat[CDIM * PROJW];
__device__ __align__(16) float g_bcat[PROJW];
__device__ __align__(16) float g_wp4[32 * 12 * 4];             // [d4][h] -> float4 of 4 consecutive d
__device__ __align__(16) float g_proj[NTOK * PROJW];           // q|k|v|qpts|kpts
__device__ __align__(16) float g_qg[NTOK * HEADS * 12];        // [n][h][y*4+p]
__device__ __align__(16) float g_sq[NTOK * HEADS];             // [n][h]
__device__ __align__(16) float g_kgT[HEADS * NTOK * 12];       // [h][m][12]
__device__ __align__(16) float g_skT[HEADS * NTOK];            // [h][m]
__device__ __align__(16) float g_bias[(size_t)HEADS * NTOK * NTOK]; // [h][n][m] (50MB)
__device__ __align__(16) float g_wt[NTOK * CDIM];              // attention output
__device__ __align__(16) float g_o[NTOK * CDIM];               // after Wo

// ---------------- f32x2 packed helpers ----------------
__device__ __forceinline__ unsigned long long ffma2(unsigned long long a,
                                                    unsigned long long b,
                                                    unsigned long long c) {
    unsigned long long d;
    asm("fma.rn.f32x2 %0, %1, %2, %3;" : "=l"(d) : "l"(a), "l"(b), "l"(c));
    return d;
}
__device__ __forceinline__ float2 unpack2(unsigned long long v) {
    float2 r;
    asm("mov.b64 {%0, %1}, %2;" : "=f"(r.x), "=f"(r.y) : "l"(v));
    return r;
}

// ---------------- prep: concat weights, pack Wp ----------------
__global__ void prep_kernel(const float* __restrict__ Wq, const float* __restrict__ Wk,
                            const float* __restrict__ Wv, const float* __restrict__ Wpq,
                            const float* __restrict__ Wpk,
                            const float* __restrict__ bq, const float* __restrict__ bk,
                            const float* __restrict__ bv, const float* __restrict__ bpq,
                            const float* __restrict__ bpk, const float* __restrict__ Wp) {
    int i = blockIdx.x * blockDim.x + threadIdx.x;
    int stride = gridDim.x * blockDim.x;
    for (int e = i; e < CDIM * PROJW; e += stride) {
        int kk = e / PROJW, j = e % PROJW;
        float v = 0.f;
        if (j < 384)       v = Wq[kk * 384 + j];
        else if (j < 768)  v = Wk[kk * 384 + j - 384];
        else if (j < 1152) v = Wv[kk * 384 + j - 768];
        else if (j < 1296) v = Wpq[kk * 144 + j - 1152];
        else if (j < 1440) v = Wpk[kk * 144 + j - 1296];
        g_wcat[e] = v;
    }
    if (i < PROJW) {
        int j = i; float v = 0.f;
        if (j < 384)       v = bq[j];
        else if (j < 768)  v = bk[j - 384];
        else if (j < 1152) v = bv[j - 768];
        else if (j < 1296) v = bpq[j - 1152];
        else if (j < 1440) v = bpk[j - 1296];
        g_bcat[j] = v;
    }
    // g_wp4[d4*48 + h*4 + q] = Wp[(4*d4+q)*12 + h]
    if (i < 32 * 12 * 4) {
        int d4 = i / 48, r = i % 48, h = r / 4, q = r % 4;
        g_wp4[i] = Wp[(4 * d4 + q) * HEADS + h];
    }
}

// ---------------- generic fp32 GEMM: C[M,N] = A[M,K]@B[K,N] + bias ----------------
__global__ __launch_bounds__(256) void gemm_kernel(
    const float* __restrict__ A, int lda,
    const float* __restrict__ B, int ldb,
    const float* __restrict__ bias,
    float* __restrict__ C, int ldc, int K) {
    __shared__ __align__(16) float As[16 * 64];
    __shared__ __align__(16) float Bs[16 * 64];
    int t = threadIdx.x;
    int tx = t & 15, ty = t >> 4;
    int row0 = blockIdx.y * 64, col0 = blockIdx.x * 64;
    int arow = t >> 2, ak4 = t & 3;
    int bk = t >> 4, bc4 = t & 15;
    float acc[4][4];
#pragma unroll
    for (int i = 0; i < 4; i++)
#pragma unroll
        for (int j = 0; j < 4; j++) acc[i][j] = 0.f;

    for (int k0 = 0; k0 < K; k0 += 16) {
        float4 av = *reinterpret_cast<const float4*>(A + (row0 + arow) * lda + k0 + ak4 * 4);
        float4 bv = *reinterpret_cast<const float4*>(B + (k0 + bk) * ldb + col0 + bc4 * 4);
        __syncthreads();
        As[(ak4 * 4 + 0) * 64 + arow] = av.x;
        As[(ak4 * 4 + 1) * 64 + arow] = av.y;
        As[(ak4 * 4 + 2) * 64 + arow] = av.z;
        As[(ak4 * 4 + 3) * 64 + arow] = av.w;
        *reinterpret_cast<float4*>(&Bs[bk * 64 + bc4 * 4]) = bv;
        __syncthreads();
#pragma unroll
        for (int kk = 0; kk < 16; kk++) {
            float4 a = *reinterpret_cast<const float4*>(&As[kk * 64 + ty * 4]);
            float4 b = *reinterpret_cast<const float4*>(&Bs[kk * 64 + tx * 4]);
            acc[0][0] += a.x * b.x; acc[0][1] += a.x * b.y; acc[0][2] += a.x * b.z; acc[0][3] += a.x * b.w;
            acc[1][0] += a.y * b.x; acc[1][1] += a.y * b.y; acc[1][2] += a.y * b.z; acc[1][3] += a.y * b.w;
            acc[2][0] += a.z * b.x; acc[2][1] += a.z * b.y; acc[2][2] += a.z * b.z; acc[2][3] += a.z * b.w;
            acc[3][0] += a.w * b.x; acc[3][1] += a.w * b.y; acc[3][2] += a.w * b.z; acc[3][3] += a.w * b.w;
        }
    }
    float4 bb = *reinterpret_cast<const float4*>(bias + col0 + tx * 4);
#pragma unroll
    for (int i = 0; i < 4; i++) {
        float4 cv = make_float4(acc[i][0] + bb.x, acc[i][1] + bb.y,
                                acc[i][2] + bb.z, acc[i][3] + bb.w);
        *reinterpret_cast<float4*>(C + (row0 + ty * 4 + i) * ldc + col0 + tx * 4) = cv;
    }
}

// ---------------- rotate points, compute sq/sk ----------------
__global__ void rotate_kernel(const float* __restrict__ rot) {
    int idx = blockIdx.x * blockDim.x + threadIdx.x;
    if (idx >= NTOK * HEADS) return;
    int n = idx / HEADS, h = idx % HEADS;
    const float* R  = rot + n * 9;
    const float* qp = g_proj + n * PROJW + 1152 + h * 12;
    const float* kp = g_proj + n * PROJW + 1296 + h * 12;
    float* qg = g_qg + idx * 12;
    float* kg = g_kgT + (h * NTOK + n) * 12;
    float sq = 0.f, sk = 0.f;
#pragma unroll
    for (int y = 0; y < 3; y++) {
        float r0 = R[y * 3 + 0], r1 = R[y * 3 + 1], r2 = R[y * 3 + 2];
#pragma unroll
        for (int p = 0; p < 4; p++) {
            float a = r0 * qp[p] + r1 * qp[4 + p] + r2 * qp[8 + p];
            qg[y * 4 + p] = a; sq += a * a;
            float b = r0 * kp[p] + r1 * kp[4 + p] + r2 * kp[8 + p];
            kg[y * 4 + p] = b; sk += b * b;
        }
    }
    g_sq[idx] = sq;
    g_skT[h * NTOK + n] = sk;
}

// ---------------- pair bias v2: f32x2, 1 m x 12 h per thread, m-tile 128 ----------------
// dyn smem: pair tile 128x(33 float4) = 67584B, packed Wp 384 float4 = 6144B
#define PB_SMEM (128 * 33 * 16 + 384 * 16)
__global__ __launch_bounds__(128) void pair_bias2_kernel(const float* __restrict__ pair,
                                                         const float* __restrict__ bp) {
    extern __shared__ __align__(16) float smem[];
    float4* sp4 = reinterpret_cast<float4*>(smem);               // [128][33]
    float*  swp = smem + 128 * 33 * 4;                           // 1536 floats
    int t = threadIdx.x;
    int n = blockIdx.y;
    int m0 = blockIdx.x * 128;

    // stage packed Wp
#pragma unroll
    for (int i = 0; i < 3; i++)
        reinterpret_cast<float4*>(swp)[t + i * 128] = reinterpret_cast<const float4*>(g_wp4)[t + i * 128];

    // stage pair tile: 128 m x 32 float4, coalesced
    const float4* src = reinterpret_cast<const float4*>(pair + ((size_t)n * NTOK + m0) * DPAIR);
#pragma unroll
    for (int i = 0; i < 32; i++) {
        int idx = t + i * 128;
        int ml = idx >> 5, d4 = idx & 31;
        sp4[ml * 33 + d4] = src[idx];
    }
    __syncthreads();

    const ulonglong2* spU = reinterpret_cast<const ulonglong2*>(sp4);
    const ulonglong2* wpU = reinterpret_cast<const ulonglong2*>(swp);
    unsigned long long acc[12];
#pragma unroll
    for (int h = 0; h < 12; h++) acc[h] = 0ULL;

#pragma unroll 4
    for (int d4 = 0; d4 < 32; d4++) {
        ulonglong2 p = spU[t * 33 + d4];
#pragma unroll
        for (int h = 0; h < 12; h++) {
            ulonglong2 ww = wpU[d4 * 12 + h];
            acc[h] = ffma2(p.x, ww.x, acc[h]);
            acc[h] = ffma2(p.y, ww.y, acc[h]);
        }
    }
#pragma unroll
    for (int h = 0; h < 12; h++) {
        float2 r = unpack2(acc[h]);
        g_bias[((size_t)h * NTOK + n) * NTOK + m0 + t] = r.x + r.y + bp[h];
    }
}

// ---------------- fused attention v3: warp per 2 rows, lanes over m ----------------
// grid (128 n-groups of 8, 12 heads), 128 threads (4 warps, 2 rows each)
__global__ __launch_bounds__(128) void attn_kernel() {
    __shared__ __align__(16) float ks[128 * 36];   // stride 9 float4: conflict-free
    __shared__ __align__(16) float vs[128 * 36];
    __shared__ __align__(16) float kgs[128 * 20];  // stride 5 float4: conflict-free
    __shared__ float sks[128];
    __shared__ __align__(16) float qs[8 * 32];
    __shared__ __align__(16) float qgs[8 * 12];
    __shared__ float sqs[8];

    int t = threadIdx.x;
    int w = t >> 5, l = t & 31;
    int h = blockIdx.y;
    int n0 = blockIdx.x * 8;
    int nA = n0 + 2 * w, nB = nA + 1;

    const float SC  = 0.17677669529663687f;   // 32^-0.5
    const float L2E = 1.4426950408889634f;
    const float SCL = SC * L2E;

    // stage q / qg / sq for the 8 rows of this block
    if (t < 64) {
        int r = t >> 3, c4 = t & 7;
        reinterpret_cast<float4*>(qs)[t] =
            *reinterpret_cast<const float4*>(g_proj + (n0 + r) * PROJW + h * CH + c4 * 4);
    } else if (t < 88) {
        int i = t - 64; int r = i / 3, e = i % 3;
        reinterpret_cast<float4*>(qgs)[r * 3 + e] =
            *reinterpret_cast<const float4*>(g_qg + ((n0 + r) * HEADS + h) * 12 + e * 4);
    } else if (t >= 96 && t < 104) {
        sqs[t - 96] = g_sq[(n0 + t - 96) * HEADS + h];
    }
    __syncthreads();

    float4 qA[8], qB[8], qgA[3], qgB[3];
#pragma unroll
    for (int c4 = 0; c4 < 8; c4++) {
        qA[c4] = reinterpret_cast<float4*>(qs)[(2 * w) * 8 + c4];
        qB[c4] = reinterpret_cast<float4*>(qs)[(2 * w + 1) * 8 + c4];
    }
#pragma unroll
    for (int i = 0; i < 3; i++) {
        qgA[i] = reinterpret_cast<float4*>(qgs)[(2 * w) * 3 + i];
        qgB[i] = reinterpret_cast<float4*>(qgs)[(2 * w + 1) * 3 + i];
    }
    float baseA = -0.5f * SCL * sqs[2 * w];
    float baseB = -0.5f * SCL * sqs[2 * w + 1];

    float lmaxA = -1e30f, lmaxB = -1e30f, lsumA = 0.f, lsumB = 0.f;
    float4 accA[8], accB[8];
#pragma unroll
    for (int c4 = 0; c4 < 8; c4++) {
        accA[c4] = make_float4(0.f, 0.f, 0.f, 0.f);
        accB[c4] = make_float4(0.f, 0.f, 0.f, 0.f);
    }

    const size_t biasA0 = ((size_t)h * NTOK + nA) * NTOK;
    const size_t biasB0 = ((size_t)h * NTOK + nB) * NTOK;

    for (int mt = 0; mt < NTOK / 128; mt++) {
        int m0 = mt * 128;
        __syncthreads();
        // stage k, v (1024 float4 each), kg (384 float4), sk (128 floats)
#pragma unroll
        for (int i = 0; i < 8; i++) {
            int idx = t + i * 128;
            int ml = idx >> 3, c4 = idx & 7;
            reinterpret_cast<float4*>(ks)[ml * 9 + c4] =
                *reinterpret_cast<const float4*>(g_proj + (m0 + ml) * PROJW + 384 + h * CH + c4 * 4);
            reinterpret_cast<float4*>(vs)[ml * 9 + c4] =
                *reinterpret_cast<const float4*>(g_proj + (m0 + ml) * PROJW + 768 + h * CH + c4 * 4);
        }
#pragma unroll
        for (int i = 0; i < 3; i++) {
            int idx = t + i * 128;
            int ml = idx / 3, e = idx - 3 * ml;
            reinterpret_cast<float4*>(kgs)[ml * 5 + e] =
                *reinterpret_cast<const float4*>(g_kgT + (h * NTOK + m0 + ml) * 12 + e * 4);
        }
        sks[t] = g_skT[h * NTOK + m0 + t];
        __syncthreads();

        // prefetch bias (coalesced 128B per warp per load)
        float bA[4], bB[4];
#pragma unroll
        for (int j = 0; j < 4; j++) {
            bA[j] = g_bias[biasA0 + m0 + j * 32 + l];
            bB[j] = g_bias[biasB0 + m0 + j * 32 + l];
        }

        float sA[4], sB[4];
#pragma unroll
        for (int j = 0; j < 4; j++) {
            int m = j * 32 + l;
            float dA = 0.f, dB = 0.f;
#pragma unroll
            for (int c4 = 0; c4 < 8; c4++) {
                float4 kk = reinterpret_cast<float4*>(ks)[m * 9 + c4];
                dA += qA[c4].x * kk.x + qA[c4].y * kk.y + qA[c4].z * kk.z + qA[c4].w * kk.w;
                dB += qB[c4].x * kk.x + qB[c4].y * kk.y + qB[c4].z * kk.z + qB[c4].w * kk.w;
            }
#pragma unroll
            for (int i = 0; i < 3; i++) {
                float4 kg = reinterpret_cast<float4*>(kgs)[m * 5 + i];
                dA += qgA[i].x * kg.x + qgA[i].y * kg.y + qgA[i].z * kg.z + qgA[i].w * kg.w;
                dB += qgB[i].x * kg.x + qgB[i].y * kg.y + qgB[i].z * kg.z + qgB[i].w * kg.w;
            }
            float skv = -0.5f * SCL * sks[m];
            sA[j] = SCL * dA + baseA + skv + L2E * bA[j];
            sB[j] = SCL * dB + baseB + skv + L2E * bB[j];
        }

        float tmA = fmaxf(fmaxf(sA[0], sA[1]), fmaxf(sA[2], sA[3]));
        float tmB = fmaxf(fmaxf(sB[0], sB[1]), fmaxf(sB[2], sB[3]));
        float nmA = fmaxf(lmaxA, tmA), nmB = fmaxf(lmaxB, tmB);
        float cA = exp2f(lmaxA - nmA), cB = exp2f(lmaxB - nmB);
        lmaxA = nmA; lmaxB = nmB;
        lsumA *= cA; lsumB *= cB;
#pragma unroll
        for (int c4 = 0; c4 < 8; c4++) {
            accA[c4].x *= cA; accA[c4].y *= cA; accA[c4].z *= cA; accA[c4].w *= cA;
            accB[c4].x *= cB; accB[c4].y *= cB; accB[c4].z *= cB; accB[c4].w *= cB;
        }
#pragma unroll
        for (int j = 0; j < 4; j++) {
            int m = j * 32 + l;
            float pA = exp2f(sA[j] - lmaxA);
            float pB = exp2f(sB[j] - lmaxB);
            lsumA += pA; lsumB += pB;
#pragma unroll
            for (int c4 = 0; c4 < 8; c4++) {
                float4 vv = reinterpret_cast<float4*>(vs)[m * 9 + c4];
                accA[c4].x += pA * vv.x; accA[c4].y += pA * vv.y;
                accA[c4].z += pA * vv.z; accA[c4].w += pA * vv.w;
                accB[c4].x += pB * vv.x; accB[c4].y += pB * vv.y;
                accB[c4].z += pB * vv.z; accB[c4].w += pB * vv.w;
            }
        }
    }

    // merge lanes (each lane holds partial softmax over its m subset)
    __syncthreads();           // done reading ks everywhere; reuse as scratch
    float* scr = ks + w * 1056;  // 32 lanes x 33 floats per warp

    // ---- row A ----
    {
        float gm = lmaxA;
#pragma unroll
        for (int o = 16; o > 0; o >>= 1) gm = fmaxf(gm, __shfl_xor_sync(0xffffffffu, gm, o));
        float f = exp2f(lmaxA - gm);
        float ls = lsumA * f;
#pragma unroll
        for (int o = 16; o > 0; o >>= 1) ls += __shfl_xor_sync(0xffffffffu, ls, o);
#pragma unroll
        for (int c4 = 0; c4 < 8; c4++) {
            scr[l * 33 + c4 * 4 + 0] = accA[c4].x * f;
            scr[l * 33 + c4 * 4 + 1] = accA[c4].y * f;
            scr[l * 33 + c4 * 4 + 2] = accA[c4].z * f;
            scr[l * 33 + c4 * 4 + 3] = accA[c4].w * f;
        }
        __syncwarp();
        float s = 0.f;
#pragma unroll
        for (int src = 0; src < 32; src++) s += scr[src * 33 + l];
        g_wt[nA * CDIM + h * CH + l] = s / ls;
        __syncwarp();
    }
    // ---- row B ----
    {
        float gm = lmaxB;
#pragma unroll
        for (int o = 16; o > 0; o >>= 1) gm = fmaxf(gm, __shfl_xor_sync(0xffffffffu, gm, o));
        float f = exp2f(lmaxB - gm);
        float ls = lsumB * f;
#pragma unroll
        for (int o = 16; o > 0; o >>= 1) ls += __shfl_xor_sync(0xffffffffu, ls, o);
#pragma unroll
        for (int c4 = 0; c4 < 8; c4++) {
            scr[l * 33 + c4 * 4 + 0] = accB[c4].x * f;
            scr[l * 33 + c4 * 4 + 1] = accB[c4].y * f;
            scr[l * 33 + c4 * 4 + 2] = accB[c4].z * f;
            scr[l * 33 + c4 * 4 + 3] = accB[c4].w * f;
        }
        __syncwarp();
        float s = 0.f;
#pragma unroll
        for (int src = 0; src < 32; src++) s += scr[src * 33 + l];
        g_wt[nB * CDIM + h * CH + l] = s / ls;
    }
}

// ---------------- residual + LayerNorm ----------------
__global__ __launch_bounds__(128) void ln_kernel(const float* __restrict__ single,
                                                 const float* __restrict__ gamma,
                                                 const float* __restrict__ beta,
                                                 float* __restrict__ out) {
    __shared__ float xr[CDIM];
    __shared__ float red[4];
    int n = blockIdx.x, t = threadIdx.x;
    float s = 0.f;
    for (int c = t; c < CDIM; c += 128) {
        float x = single[n * CDIM + c] + g_o[n * CDIM + c];
        xr[c] = x; s += x;
    }
#pragma unroll
    for (int o = 16; o > 0; o >>= 1) s += __shfl_xor_sync(0xffffffffu, s, o);
    if ((t & 31) == 0) red[t >> 5] = s;
    __syncthreads();
    float mu = (red[0] + red[1] + red[2] + red[3]) * (1.f / CDIM);
    float v = 0.f;
    for (int c = t; c < CDIM; c += 128) { float d = xr[c] - mu; v += d * d; }
#pragma unroll
    for (int o = 16; o > 0; o >>= 1) v += __shfl_xor_sync(0xffffffffu, v, o);
    __syncthreads();
    if ((t & 31) == 0) red[t >> 5] = v;
    __syncthreads();
    float var = (red[0] + red[1] + red[2] + red[3]) * (1.f / CDIM);
    float inv = rsqrtf(var + LEPS);
    for (int c = t; c < CDIM; c += 128)
        out[n * CDIM + c] = (xr[c] - mu) * inv * gamma[c] + beta[c];
}

// ---------------- launch ----------------
extern "C" void kernel_launch(void* const* d_in, const int* in_sizes, int n_in,
                              void* d_out, int out_size) {
    (void)in_sizes; (void)n_in; (void)out_size;
    const float* single = (const float*)d_in[0];
    const float* pair   = (const float*)d_in[1];
    const float* rot    = (const float*)d_in[2];
    // d_in[3] translations: unused by the reference
    const float* Wq  = (const float*)d_in[4];  const float* bq  = (const float*)d_in[5];
    const float* Wk  = (const float*)d_in[6];  const float* bk  = (const float*)d_in[7];
    const float* Wv  = (const float*)d_in[8];  const float* bv  = (const float*)d_in[9];
    const float* Wp  = (const float*)d_in[10]; const float* bp  = (const float*)d_in[11];
    const float* Wpq = (const float*)d_in[12]; const float* bpq = (const float*)d_in[13];
    const float* Wpk = (const float*)d_in[14]; const float* bpk = (const float*)d_in[15];
    const float* Wo  = (const float*)d_in[16]; const float* bo  = (const float*)d_in[17];
    const float* gamma = (const float*)d_in[18];
    const float* beta  = (const float*)d_in[19];
    float* out = (float*)d_out;

    float *p_wcat, *p_bcat, *p_proj, *p_wt, *p_o;
    cudaGetSymbolAddress((void**)&p_wcat, g_wcat);
    cudaGetSymbolAddress((void**)&p_bcat, g_bcat);
    cudaGetSymbolAddress((void**)&p_proj, g_proj);
    cudaGetSymbolAddress((void**)&p_wt, g_wt);
    cudaGetSymbolAddress((void**)&p_o, g_o);

    // host-side attribute set; not stream-ordered, safe during graph capture
    cudaFuncSetAttribute(pair_bias2_kernel,
                         cudaFuncAttributeMaxDynamicSharedMemorySize, PB_SMEM);

    prep_kernel<<<64, 256>>>(Wq, Wk, Wv, Wpq, Wpk, bq, bk, bv, bpq, bpk, Wp);
    gemm_kernel<<<dim3(PROJW / 64, NTOK / 64), 256>>>(single, CDIM, p_wcat, PROJW,
                                                      p_bcat, p_proj, PROJW, CDIM);
    rotate_kernel<<<48, 256>>>(rot);
    pair_bias2_kernel<<<dim3(8, NTOK), 128, PB_SMEM>>>(pair, bp);
    attn_kernel<<<dim3(128, HEADS), 128>>>();
    gemm_kernel<<<dim3(CDIM / 64, NTOK / 64), 256>>>(p_wt, CDIM, Wo, CDIM,
                                                     bo, p_o, CDIM, CDIM);
    ln_kernel<<<NTOK, 128>>>(single, gamma, beta, out);
}